// round 1
// baseline (speedup 1.0000x reference)
#include <cuda_runtime.h>
#include <math.h>

#define NPTS 8192
#define DIN  512
#define HID  1024
#define EMBD 64
#define NEFF 2
#define NCONS 62   // EMBD - NEFF
#define NCLS 16
#define MARGIN 0.01f

// ---------------- scratch (static device globals; no allocation) ----------------
__device__ float g_h1[NPTS * HID];
__device__ float g_emb[NPTS * EMBD];
__device__ float g_h2[NPTS * HID];
__device__ float g_sq[NPTS];
__device__ int   g_lbl[NPTS];
__device__ int   g_cnt[NCLS];
__device__ int   g_off[NCLS + 1];
__device__ int   g_cur[NCLS];
__device__ int   g_perm[NPTS];
__device__ int   g_tileoff[NCLS + 1];
__device__ float g_msum[NCLS * NCONS];
__device__ float g_T[NCLS];
__device__ float g_cdiff;

// ---------------- init: zero all per-launch accumulators ----------------
__global__ void init_kernel() {
    int t = threadIdx.x;
    for (int i = t; i < NCLS * NCONS; i += blockDim.x) g_msum[i] = 0.f;
    if (t < NCLS) { g_T[t] = 0.f; g_cnt[t] = 0; g_cur[t] = 0; }
    if (t == 0) g_cdiff = 0.f;
}

// ---------------- tiled SGEMM with bias + optional tanh epilogue ----------------
// C[M,N] = act(A[M,K] @ B[K,N] + bias[N]); all dims divisible by tiles.
template<int BM, int BN, int BK, int TM, int TN, bool DOTANH>
__global__ __launch_bounds__((BM / TM) * (BN / TN))
void sgemm_bias_act(const float* __restrict__ A, int lda,
                    const float* __restrict__ B, int ldb,
                    const float* __restrict__ bias,
                    float* __restrict__ C, int ldc, int K)
{
    constexpr int THREADS = (BM / TM) * (BN / TN);
    constexpr int TCOLS = BN / TN;
    __shared__ float As[BK][BM + 4];
    __shared__ float Bs[BK][BN];

    const int tid = threadIdx.x;
    const int ty = tid / TCOLS;
    const int tx = tid % TCOLS;
    const int rowBase = blockIdx.y * BM;
    const int colBase = blockIdx.x * BN;

    const float* Ab = A + (long)rowBase * lda;
    const float* Bb = B + colBase;

    float acc[TM][TN];
#pragma unroll
    for (int m = 0; m < TM; m++)
#pragma unroll
        for (int n = 0; n < TN; n++) acc[m][n] = 0.f;

    for (int k0 = 0; k0 < K; k0 += BK) {
#pragma unroll
        for (int i = 0; i < (BM * BK) / THREADS; i++) {
            int idx = tid + i * THREADS;
            int r = idx / BK, c = idx % BK;
            As[c][r] = Ab[(long)r * lda + (k0 + c)];
        }
#pragma unroll
        for (int i = 0; i < (BK * BN) / THREADS; i++) {
            int idx = tid + i * THREADS;
            int r = idx / BN, c = idx % BN;
            Bs[r][c] = Bb[(long)(k0 + r) * ldb + c];
        }
        __syncthreads();
#pragma unroll
        for (int k = 0; k < BK; k++) {
            float ra[TM], rb[TN];
#pragma unroll
            for (int m = 0; m < TM; m += 4) {
                float4 v = *reinterpret_cast<const float4*>(&As[k][ty * TM + m]);
                ra[m] = v.x; ra[m + 1] = v.y; ra[m + 2] = v.z; ra[m + 3] = v.w;
            }
#pragma unroll
            for (int n = 0; n < TN; n += 4) {
                float4 v = *reinterpret_cast<const float4*>(&Bs[k][tx * TN + n]);
                rb[n] = v.x; rb[n + 1] = v.y; rb[n + 2] = v.z; rb[n + 3] = v.w;
            }
#pragma unroll
            for (int m = 0; m < TM; m++)
#pragma unroll
                for (int n = 0; n < TN; n++)
                    acc[m][n] += ra[m] * rb[n];
        }
        __syncthreads();
    }

#pragma unroll
    for (int m = 0; m < TM; m++) {
        int row = rowBase + ty * TM + m;
#pragma unroll
        for (int n = 0; n < TN; n += 4) {
            int col = colBase + tx * TN + n;
            float4 v;
            v.x = acc[m][n + 0] + bias[col + 0];
            v.y = acc[m][n + 1] + bias[col + 1];
            v.z = acc[m][n + 2] + bias[col + 2];
            v.w = acc[m][n + 3] + bias[col + 3];
            if (DOTANH) {
                v.x = tanhf(v.x); v.y = tanhf(v.y);
                v.z = tanhf(v.z); v.w = tanhf(v.w);
            }
            *reinterpret_cast<float4*>(&C[(long)row * ldc + col]) = v;
        }
    }
}

// ---------------- per-point / per-class statistics ----------------
__global__ void stats_kernel(const float* __restrict__ x) {
    __shared__ float sm[NCLS * NCONS];
    __shared__ float sT[NCLS];
    __shared__ int   sC[NCLS];
    int tid = threadIdx.x;
    for (int i = tid; i < NCLS * NCONS; i += blockDim.x) sm[i] = 0.f;
    if (tid < NCLS) { sT[tid] = 0.f; sC[tid] = 0; }
    __syncthreads();

    int i = blockIdx.x * blockDim.x + tid;       // exact coverage (32*256 = 8192)
    int l = (int)x[(long)i * (DIN + 1)];
    const float* e = g_emb + (long)i * EMBD + NEFF;
    float sq = 0.f;
#pragma unroll
    for (int d = 0; d < NCONS; d++) {
        float v = e[d];
        sq += v * v;
        atomicAdd(&sm[l * NCONS + d], v);
    }
    g_sq[i] = sq;
    g_lbl[i] = l;
    atomicAdd(&sT[l], sq);
    atomicAdd(&sC[l], 1);
    __syncthreads();

    for (int j = tid; j < NCLS * NCONS; j += blockDim.x) atomicAdd(&g_msum[j], sm[j]);
    if (tid < NCLS) {
        atomicAdd(&g_T[tid], sT[tid]);
        atomicAdd(&g_cnt[tid], sC[tid]);
    }
}

// ---------------- counting-sort offsets + tile offsets ----------------
__global__ void offsets_kernel() {
    if (threadIdx.x == 0 && blockIdx.x == 0) {
        int acc = 0, tacc = 0;
        for (int k = 0; k < NCLS; k++) {
            g_off[k] = acc; acc += g_cnt[k];
            g_cur[k] = 0;
            int t = (g_cnt[k] + 31) >> 5;
            g_tileoff[k] = tacc; tacc += t * t;
        }
        g_off[NCLS] = acc;
        g_tileoff[NCLS] = tacc;
    }
}

__global__ void scatter_kernel() {
    int i = blockIdx.x * blockDim.x + threadIdx.x;
    int l = g_lbl[i];
    int pos = g_off[l] + atomicAdd(&g_cur[l], 1);
    g_perm[pos] = i;
}

// ---------------- same-class pairwise C_diff (persistent tile loop) ----------------
__global__ __launch_bounds__(256)
void pairwise_kernel() {
    __shared__ float Ci[32][NCONS + 1];   // pad to 63: conflict-free
    __shared__ float Cj[32][NCONS + 1];
    __shared__ float sqi[32], sqj[32];
    __shared__ float red[256];

    int tid = threadIdx.x;
    int total = g_tileoff[NCLS];
    float accT = 0.f;

    for (int w = blockIdx.x; w < total; w += gridDim.x) {
        int k = 0;
        while (g_tileoff[k + 1] <= w) k++;
        int n = g_cnt[k];
        int tpd = (n + 31) >> 5;
        int local = w - g_tileoff[k];
        int ti = local / tpd, tj = local % tpd;
        int base = g_off[k];
        int ni = min(32, n - ti * 32);
        int nj = min(32, n - tj * 32);

        __syncthreads();   // protect shared reuse across tiles
        for (int idx = tid; idx < 32 * NCONS; idx += blockDim.x) {
            int r = idx / NCONS, d = idx % NCONS;
            int a = ti * 32 + r;
            if (a < n) {
                int gi = g_perm[base + a];
                Ci[r][d] = g_emb[(long)gi * EMBD + NEFF + d];
                if (d == 0) sqi[r] = g_sq[gi];
            }
            int b = tj * 32 + r;
            if (b < n) {
                int gj = g_perm[base + b];
                Cj[r][d] = g_emb[(long)gj * EMBD + NEFF + d];
                if (d == 0) sqj[r] = g_sq[gj];
            }
        }
        __syncthreads();

        int b = tid & 31;        // varies across warp -> conflict-free Cj reads
        int a0 = tid >> 5;       // uniform across warp -> broadcast Ci reads
        if (b < nj) {
            float sj = sqj[b];
#pragma unroll
            for (int m = 0; m < 4; m++) {
                int a = a0 + m * 8;
                if (a < ni) {
                    float dot = 0.f;
#pragma unroll
                    for (int d = 0; d < NCONS; d++) dot += Ci[a][d] * Cj[b][d];
                    float D = fmaxf(sqi[a] + sj - 2.f * dot, 0.f) * (1.f / NCONS);
                    float t = MARGIN - D;
                    if (t > 0.f) accT += t;
                }
            }
        }
    }

    red[tid] = accT;
    __syncthreads();
    for (int s = 128; s > 0; s >>= 1) {
        if (tid < s) red[tid] += red[tid + s];
        __syncthreads();
    }
    if (tid == 0 && red[0] != 0.f) atomicAdd(&g_cdiff, red[0]);
}

// ---------------- finalize: closed-form C_sim, normalize C_diff ----------------
__global__ void finalize_kernel(float* __restrict__ out) {
    if (threadIdx.x != 0 || blockIdx.x != 0) return;
    float M[NCONS];
#pragma unroll
    for (int d = 0; d < NCONS; d++) M[d] = 0.f;
    float sumTw = 0.f, summ2 = 0.f;
    long long sumn2 = 0;
    for (int k = 0; k < NCLS; k++) {
        int n = g_cnt[k];
        sumn2 += (long long)n * n;
        sumTw += g_T[k] * (float)(NPTS - n);
        float mm = 0.f;
        for (int d = 0; d < NCONS; d++) {
            float v = g_msum[k * NCONS + d];
            M[d] += v;
            mm += v * v;
        }
        summ2 += mm;
    }
    float MM = 0.f;
    for (int d = 0; d < NCONS; d++) MM += M[d] * M[d];

    double ndiff = (double)NPTS * (double)NPTS - (double)sumn2;
    float raw = 2.f * sumTw - 2.f * (MM - summ2);
    float csim = raw * (1.f / NCONS) / (float)(ndiff + 1.0);
    float cdiff = g_cdiff / (float)((double)NPTS * (double)NPTS - ndiff + 1.0);

    out[(long)NPTS * DIN]     = csim;
    out[(long)NPTS * DIN + 1] = cdiff;
}

// ---------------- launch ----------------
extern "C" void kernel_launch(void* const* d_in, const int* in_sizes, int n_in,
                              void* d_out, int out_size) {
    const float* x  = (const float*)d_in[0];
    const float* W1 = (const float*)d_in[1];
    const float* b1 = (const float*)d_in[2];
    const float* W2 = (const float*)d_in[3];
    const float* b2 = (const float*)d_in[4];
    const float* W3 = (const float*)d_in[5];
    const float* b3 = (const float*)d_in[6];
    const float* W4 = (const float*)d_in[7];
    const float* b4 = (const float*)d_in[8];
    float* out = (float*)d_out;

    void *p_h1, *p_emb, *p_h2;
    cudaGetSymbolAddress(&p_h1,  g_h1);
    cudaGetSymbolAddress(&p_emb, g_emb);
    cudaGetSymbolAddress(&p_h2,  g_h2);
    float* h1  = (float*)p_h1;
    float* emb = (float*)p_emb;
    float* h2  = (float*)p_h2;

    init_kernel<<<1, 256>>>();

    // h1 = tanh(data @ W1 + b1)   data = x[:,1:], lda=513
    {
        dim3 grid(HID / 128, NPTS / 128);
        sgemm_bias_act<128, 128, 16, 8, 8, true><<<grid, 256>>>(
            x + 1, DIN + 1, W1, HID, b1, h1, HID, DIN);
    }
    // emb = h1 @ W2 + b2
    {
        dim3 grid(EMBD / 64, NPTS / 128);
        sgemm_bias_act<128, 64, 16, 8, 4, false><<<grid, 256>>>(
            h1, HID, W2, EMBD, b2, emb, EMBD, HID);
    }
    // h2 = tanh(emb @ W3 + b3)
    {
        dim3 grid(HID / 128, NPTS / 128);
        sgemm_bias_act<128, 128, 16, 8, 8, true><<<grid, 256>>>(
            emb, EMBD, W3, HID, b3, h2, HID, EMBD);
    }
    // decoded = h2 @ W4 + b4  -> first NPTS*DIN floats of out
    {
        dim3 grid(DIN / 128, NPTS / 128);
        sgemm_bias_act<128, 128, 16, 8, 8, false><<<grid, 256>>>(
            h2, HID, W4, DIN, b4, out, DIN, HID);
    }

    stats_kernel<<<NPTS / 256, 256>>>(x);
    offsets_kernel<<<1, 32>>>();
    scatter_kernel<<<NPTS / 256, 256>>>();
    pairwise_kernel<<<8192, 256>>>();
    finalize_kernel<<<1, 32>>>(out);
}

// round 2
// speedup vs baseline: 1.0951x; 1.0951x over previous
#include <cuda_runtime.h>
#include <math.h>

#define NPTS 8192
#define DIN  512
#define HID  1024
#define EMBD 64
#define NEFF 2
#define NCONS 62   // EMBD - NEFF
#define NCLS 16
#define MARGIN 0.01f

typedef unsigned long long ull;

// ---------------- scratch (static device globals; no allocation) ----------------
__device__ float g_h1[NPTS * HID];
__device__ float g_emb[NPTS * EMBD];
__device__ float g_h2[NPTS * HID];
__device__ float g_sq[NPTS];
__device__ int   g_lbl[NPTS];
__device__ int   g_cnt[NCLS];
__device__ int   g_off[NCLS + 1];
__device__ int   g_cur[NCLS];
__device__ int   g_perm[NPTS];
__device__ int   g_tileoff[NCLS + 1];
__device__ float g_msum[NCLS * NCONS];
__device__ float g_T[NCLS];
__device__ float g_cdiff;

// ---------------- packed f32x2 helpers (sm_100+) ----------------
__device__ __forceinline__ ull fma2(ull a, ull b, ull c) {
    ull d;
    asm("fma.rn.f32x2 %0, %1, %2, %3;" : "=l"(d) : "l"(a), "l"(b), "l"(c));
    return d;
}
__device__ __forceinline__ ull pack2(float v) {
    ull d;
    asm("mov.b64 %0, {%1, %1};" : "=l"(d) : "r"(__float_as_uint(v)));
    return d;
}
__device__ __forceinline__ void unpack2(ull p, float& lo, float& hi) {
    unsigned a, b;
    asm("mov.b64 {%0, %1}, %2;" : "=r"(a), "=r"(b) : "l"(p));
    lo = __uint_as_float(a); hi = __uint_as_float(b);
}

// ---------------- init: zero all per-launch accumulators ----------------
__global__ void init_kernel() {
    int t = threadIdx.x;
    for (int i = t; i < NCLS * NCONS; i += blockDim.x) g_msum[i] = 0.f;
    if (t < NCLS) { g_T[t] = 0.f; g_cnt[t] = 0; g_cur[t] = 0; }
    if (t == 0) g_cdiff = 0.f;
}

// ---------------- double-buffered SGEMM, f32x2 FMA, bias + optional tanh ----------------
// C[M,N] = act(A[M,K] @ B[K,N] + bias[N]); dims divisible by tiles; K % BK == 0.
template<int BM, int BN, int BK, int TM, int TN, bool DOTANH>
__global__ __launch_bounds__(256, 2)
void sgemm2(const float* __restrict__ A, int lda,
            const float* __restrict__ B, int ldb,
            const float* __restrict__ bias,
            float* __restrict__ C, int ldc, int K)
{
    constexpr int THREADS = 256;
    constexpr int TCOLS = BN / TN;
    constexpr int AL = BM * BK / THREADS;   // A floats per thread per tile
    constexpr int BL = BK * BN / THREADS;   // B floats per thread per tile
    static_assert((BM / TM) * TCOLS == THREADS, "thread shape");
    static_assert(TM % 4 == 0 && TN % 4 == 0, "vector shape");

    __shared__ float As[2][BK][BM + 4];
    __shared__ float Bs[2][BK][BN];

    const int tid = threadIdx.x;
    const int ty = tid / TCOLS;
    const int tx = tid % TCOLS;
    const int rowBase = blockIdx.y * BM;
    const int colBase = blockIdx.x * BN;

    const float* Ab = A + (long)rowBase * lda;
    const float* Bb = B + colBase;

    ull acc[TM][TN / 2];
#pragma unroll
    for (int m = 0; m < TM; m++)
#pragma unroll
        for (int j = 0; j < TN / 2; j++) acc[m][j] = 0ull;

    // prologue: load tile 0 into buffer 0
#pragma unroll
    for (int i = 0; i < AL; i++) {
        int idx = tid + i * THREADS;
        int r = idx / BK, c = idx % BK;
        As[0][c][r] = Ab[(long)r * lda + c];
    }
#pragma unroll
    for (int i = 0; i < BL; i++) {
        int idx = tid + i * THREADS;
        int r = idx / BN, c = idx % BN;
        Bs[0][r][c] = Bb[(long)r * ldb + c];
    }
    __syncthreads();

    const int nIter = K / BK;
    float ldrA[AL], ldrB[BL];

    for (int it = 0; it < nIter; it++) {
        const int buf = it & 1;
        // prefetch next tile into registers (LDGs in flight during compute)
        if (it + 1 < nIter) {
            const int k0 = (it + 1) * BK;
#pragma unroll
            for (int i = 0; i < AL; i++) {
                int idx = tid + i * THREADS;
                int r = idx / BK, c = idx % BK;
                ldrA[i] = Ab[(long)r * lda + k0 + c];
            }
#pragma unroll
            for (int i = 0; i < BL; i++) {
                int idx = tid + i * THREADS;
                int r = idx / BN, c = idx % BN;
                ldrB[i] = Bb[(long)(k0 + r) * ldb + c];
            }
        }

        // compute on current buffer
#pragma unroll
        for (int k = 0; k < BK; k++) {
            float ra[TM];
            ull rb2[TN / 2];
#pragma unroll
            for (int m = 0; m < TM; m += 4) {
                float4 v = *reinterpret_cast<const float4*>(&As[buf][k][ty * TM + m]);
                ra[m] = v.x; ra[m + 1] = v.y; ra[m + 2] = v.z; ra[m + 3] = v.w;
            }
            const ull* bp = reinterpret_cast<const ull*>(&Bs[buf][k][tx * TN]);
#pragma unroll
            for (int j = 0; j < TN / 2; j++) rb2[j] = bp[j];
#pragma unroll
            for (int m = 0; m < TM; m++) {
                ull a2 = pack2(ra[m]);
#pragma unroll
                for (int j = 0; j < TN / 2; j++)
                    acc[m][j] = fma2(a2, rb2[j], acc[m][j]);
            }
        }

        // stage prefetched tile into the other buffer (consumed last iter -> safe)
        if (it + 1 < nIter) {
            const int nb = buf ^ 1;
#pragma unroll
            for (int i = 0; i < AL; i++) {
                int idx = tid + i * THREADS;
                int r = idx / BK, c = idx % BK;
                As[nb][c][r] = ldrA[i];
            }
#pragma unroll
            for (int i = 0; i < BL; i++) {
                int idx = tid + i * THREADS;
                int r = idx / BN, c = idx % BN;
                Bs[nb][r][c] = ldrB[i];
            }
        }
        __syncthreads();
    }

    // epilogue
#pragma unroll
    for (int m = 0; m < TM; m++) {
        int row = rowBase + ty * TM + m;
        float* Crow = &C[(long)row * ldc + colBase + tx * TN];
        const float* brow = &bias[colBase + tx * TN];
#pragma unroll
        for (int j = 0; j < TN / 2; j++) {
            float lo, hi;
            unpack2(acc[m][j], lo, hi);
            lo += brow[2 * j];
            hi += brow[2 * j + 1];
            if (DOTANH) { lo = tanhf(lo); hi = tanhf(hi); }
            Crow[2 * j]     = lo;
            Crow[2 * j + 1] = hi;
        }
    }
}

// ---------------- per-point / per-class statistics ----------------
__global__ void stats_kernel(const float* __restrict__ x) {
    __shared__ float sm[NCLS * NCONS];
    __shared__ float sT[NCLS];
    __shared__ int   sC[NCLS];
    int tid = threadIdx.x;
    for (int i = tid; i < NCLS * NCONS; i += blockDim.x) sm[i] = 0.f;
    if (tid < NCLS) { sT[tid] = 0.f; sC[tid] = 0; }
    __syncthreads();

    int i = blockIdx.x * blockDim.x + tid;       // exact coverage (32*256 = 8192)
    int l = (int)x[(long)i * (DIN + 1)];
    const float* e = g_emb + (long)i * EMBD + NEFF;
    float sq = 0.f;
#pragma unroll
    for (int d = 0; d < NCONS; d++) {
        float v = e[d];
        sq += v * v;
        atomicAdd(&sm[l * NCONS + d], v);
    }
    g_sq[i] = sq;
    g_lbl[i] = l;
    atomicAdd(&sT[l], sq);
    atomicAdd(&sC[l], 1);
    __syncthreads();

    for (int j = tid; j < NCLS * NCONS; j += blockDim.x) atomicAdd(&g_msum[j], sm[j]);
    if (tid < NCLS) {
        atomicAdd(&g_T[tid], sT[tid]);
        atomicAdd(&g_cnt[tid], sC[tid]);
    }
}

// ---------------- counting-sort offsets + tile offsets ----------------
__global__ void offsets_kernel() {
    if (threadIdx.x == 0 && blockIdx.x == 0) {
        int acc = 0, tacc = 0;
        for (int k = 0; k < NCLS; k++) {
            g_off[k] = acc; acc += g_cnt[k];
            g_cur[k] = 0;
            int t = (g_cnt[k] + 31) >> 5;
            g_tileoff[k] = tacc; tacc += t * t;
        }
        g_off[NCLS] = acc;
        g_tileoff[NCLS] = tacc;
    }
}

__global__ void scatter_kernel() {
    int i = blockIdx.x * blockDim.x + threadIdx.x;
    int l = g_lbl[i];
    int pos = g_off[l] + atomicAdd(&g_cur[l], 1);
    g_perm[pos] = i;
}

// ---------------- same-class pairwise C_diff (persistent tile loop) ----------------
__global__ __launch_bounds__(256)
void pairwise_kernel() {
    __shared__ float Ci[32][NCONS + 1];   // pad to 63: conflict-free
    __shared__ float Cj[32][NCONS + 1];
    __shared__ float sqi[32], sqj[32];
    __shared__ float red[256];

    int tid = threadIdx.x;
    int total = g_tileoff[NCLS];
    float accT = 0.f;

    for (int w = blockIdx.x; w < total; w += gridDim.x) {
        int k = 0;
        while (g_tileoff[k + 1] <= w) k++;
        int n = g_cnt[k];
        int tpd = (n + 31) >> 5;
        int local = w - g_tileoff[k];
        int ti = local / tpd, tj = local % tpd;
        int base = g_off[k];
        int ni = min(32, n - ti * 32);
        int nj = min(32, n - tj * 32);

        __syncthreads();   // protect shared reuse across tiles
        for (int idx = tid; idx < 32 * NCONS; idx += blockDim.x) {
            int r = idx / NCONS, d = idx % NCONS;
            int a = ti * 32 + r;
            if (a < n) {
                int gi = g_perm[base + a];
                Ci[r][d] = g_emb[(long)gi * EMBD + NEFF + d];
                if (d == 0) sqi[r] = g_sq[gi];
            }
            int b = tj * 32 + r;
            if (b < n) {
                int gj = g_perm[base + b];
                Cj[r][d] = g_emb[(long)gj * EMBD + NEFF + d];
                if (d == 0) sqj[r] = g_sq[gj];
            }
        }
        __syncthreads();

        int b = tid & 31;        // varies across warp -> conflict-free Cj reads
        int a0 = tid >> 5;       // uniform across warp -> broadcast Ci reads
        if (b < nj) {
            float sj = sqj[b];
#pragma unroll
            for (int m = 0; m < 4; m++) {
                int a = a0 + m * 8;
                if (a < ni) {
                    float dot = 0.f;
#pragma unroll
                    for (int d = 0; d < NCONS; d++) dot += Ci[a][d] * Cj[b][d];
                    float D = fmaxf(sqi[a] + sj - 2.f * dot, 0.f) * (1.f / NCONS);
                    float t = MARGIN - D;
                    if (t > 0.f) accT += t;
                }
            }
        }
    }

    red[tid] = accT;
    __syncthreads();
    for (int s = 128; s > 0; s >>= 1) {
        if (tid < s) red[tid] += red[tid + s];
        __syncthreads();
    }
    if (tid == 0 && red[0] != 0.f) atomicAdd(&g_cdiff, red[0]);
}

// ---------------- finalize: closed-form C_sim, normalize C_diff ----------------
__global__ void finalize_kernel(float* __restrict__ out) {
    if (threadIdx.x != 0 || blockIdx.x != 0) return;
    float M[NCONS];
#pragma unroll
    for (int d = 0; d < NCONS; d++) M[d] = 0.f;
    float sumTw = 0.f, summ2 = 0.f;
    long long sumn2 = 0;
    for (int k = 0; k < NCLS; k++) {
        int n = g_cnt[k];
        sumn2 += (long long)n * n;
        sumTw += g_T[k] * (float)(NPTS - n);
        float mm = 0.f;
        for (int d = 0; d < NCONS; d++) {
            float v = g_msum[k * NCONS + d];
            M[d] += v;
            mm += v * v;
        }
        summ2 += mm;
    }
    float MM = 0.f;
    for (int d = 0; d < NCONS; d++) MM += M[d] * M[d];

    double ndiff = (double)NPTS * (double)NPTS - (double)sumn2;
    float raw = 2.f * sumTw - 2.f * (MM - summ2);
    float csim = raw * (1.f / NCONS) / (float)(ndiff + 1.0);
    float cdiff = g_cdiff / (float)((double)NPTS * (double)NPTS - ndiff + 1.0);

    out[(long)NPTS * DIN]     = csim;
    out[(long)NPTS * DIN + 1] = cdiff;
}

// ---------------- launch ----------------
extern "C" void kernel_launch(void* const* d_in, const int* in_sizes, int n_in,
                              void* d_out, int out_size) {
    const float* x  = (const float*)d_in[0];
    const float* W1 = (const float*)d_in[1];
    const float* b1 = (const float*)d_in[2];
    const float* W2 = (const float*)d_in[3];
    const float* b2 = (const float*)d_in[4];
    const float* W3 = (const float*)d_in[5];
    const float* b3 = (const float*)d_in[6];
    const float* W4 = (const float*)d_in[7];
    const float* b4 = (const float*)d_in[8];
    float* out = (float*)d_out;

    void *p_h1, *p_emb, *p_h2;
    cudaGetSymbolAddress(&p_h1,  g_h1);
    cudaGetSymbolAddress(&p_emb, g_emb);
    cudaGetSymbolAddress(&p_h2,  g_h2);
    float* h1  = (float*)p_h1;
    float* emb = (float*)p_emb;
    float* h2  = (float*)p_h2;

    init_kernel<<<1, 256>>>();

    // h1 = tanh(data @ W1 + b1)   data = x[:,1:], lda=513
    {
        dim3 grid(HID / 128, NPTS / 128);
        sgemm2<128, 128, 8, 8, 8, true><<<grid, 256>>>(
            x + 1, DIN + 1, W1, HID, b1, h1, HID, DIN);
    }
    // emb = h1 @ W2 + b2   (small N: use 64x64 tiles -> 128 blocks)
    {
        dim3 grid(EMBD / 64, NPTS / 64);
        sgemm2<64, 64, 8, 4, 4, false><<<grid, 256>>>(
            h1, HID, W2, EMBD, b2, emb, EMBD, HID);
    }
    // h2 = tanh(emb @ W3 + b3)
    {
        dim3 grid(HID / 128, NPTS / 128);
        sgemm2<128, 128, 8, 8, 8, true><<<grid, 256>>>(
            emb, EMBD, W3, HID, b3, h2, HID, EMBD);
    }
    // decoded = h2 @ W4 + b4  -> first NPTS*DIN floats of out
    {
        dim3 grid(DIN / 128, NPTS / 128);
        sgemm2<128, 128, 8, 8, 8, false><<<grid, 256>>>(
            h2, HID, W4, DIN, b4, out, DIN, HID);
    }

    stats_kernel<<<NPTS / 256, 256>>>(x);
    offsets_kernel<<<1, 32>>>();
    scatter_kernel<<<NPTS / 256, 256>>>();
    pairwise_kernel<<<4096, 256>>>();
    finalize_kernel<<<1, 32>>>(out);
}

// round 4
// speedup vs baseline: 1.4627x; 1.3357x over previous
#include <cuda_runtime.h>
#include <cuda_bf16.h>
#include <mma.h>
#include <math.h>
#include <stdint.h>

using namespace nvcuda;

#define NPTS 8192
#define DIN  512
#define HID  1024
#define EMBD 64
#define NEFF 2
#define NCONS 62   // EMBD - NEFF
#define NCLS 16
#define MARGIN 0.01f

// ---------------- scratch (static device globals; no allocation) ----------------
__device__ float g_h1[NPTS * HID];
__device__ float g_emb[NPTS * EMBD];
__device__ float g_h2[NPTS * HID];
__device__ float g_sq[NPTS];
__device__ int   g_lbl[NPTS];
__device__ int   g_cnt[NCLS];
__device__ int   g_off[NCLS + 1];
__device__ int   g_cur[NCLS];
__device__ int   g_perm[NPTS];
__device__ int   g_tileoff[NCLS + 1];
__device__ float g_msum[NCLS * NCONS];
__device__ float g_T[NCLS];
__device__ float g_cdiff;

// ================= WMMA bf16 split GEMM =================
// C[M,N] = act(A[M,K] @ B[K,N] + bias[N]) via D = Ahi*Bhi + Alo*Bhi + Ahi*Blo.
// 256 threads, 8 warps arranged (BM/WM) x (BN/WN). BK = 32. K % 32 == 0.
template<int BM, int BN, int WM, int WN, bool DOTANH>
__global__ __launch_bounds__(256, 2)
void hgemm(const float* __restrict__ A, int lda,
           const float* __restrict__ B, int ldb,
           const float* __restrict__ bias,
           float* __restrict__ C, int ldc, int K)
{
    constexpr int BK = 32;
    constexpr int BKP = BK + 8;     // bf16 ld stride (mult of 8)
    constexpr int BNP = BN + 8;
    constexpr int BNPF = BN + 8;    // float ld stride (mult of 4)
    constexpr int MW = BM / WM;
    constexpr int NW = BN / WN;
    static_assert(MW * NW == 8, "8 warps");
    constexpr int MFRAG = WM / 16;
    constexpr int NFRAG = WN / 16;

    __shared__ __nv_bfloat16 Ahi[BM * BKP];
    __shared__ __nv_bfloat16 Alo[BM * BKP];
    __shared__ __nv_bfloat16 Bhi[BK * BNP];
    __shared__ __nv_bfloat16 Blo[BK * BNP];
    __shared__ float biasT[16 * BNPF];

    const int tid = threadIdx.x;
    const int wid = tid >> 5;
    const int wm = wid % MW;
    const int wn = wid / MW;
    const int rowBase = blockIdx.y * BM;
    const int n0 = blockIdx.x * BN;

    const float* Ab = A + (long)rowBase * lda;

    // bias replicated over 16 rows (for accumulator-layout fragment loads)
    for (int i = tid; i < 16 * BN; i += 256)
        biasT[(i / BN) * BNPF + (i % BN)] = bias[n0 + (i % BN)];

    wmma::fragment<wmma::accumulator, 16, 16, 16, float> acc[MFRAG][NFRAG];
#pragma unroll
    for (int mf = 0; mf < MFRAG; mf++)
#pragma unroll
        for (int nf = 0; nf < NFRAG; nf++)
            wmma::fill_fragment(acc[mf][nf], 0.0f);

    const int nChunks = K / BK;
    for (int ch = 0; ch < nChunks; ch++) {
        const int k0 = ch * BK;
        __syncthreads();   // protect smem from previous iteration's readers

        // A tile: BM x 32, split hi/lo
#pragma unroll 4
        for (int i = tid; i < BM * BK; i += 256) {
            int r = i >> 5, c = i & 31;
            float v = Ab[(long)r * lda + k0 + c];
            __nv_bfloat16 h = __float2bfloat16(v);
            Ahi[r * BKP + c] = h;
            Alo[r * BKP + c] = __float2bfloat16(v - __bfloat162float(h));
        }
        // B tile: 32 x BN, split hi/lo
#pragma unroll 4
        for (int i = tid; i < BK * BN; i += 256) {
            int r = i / BN, c = i % BN;
            float v = B[(long)(k0 + r) * ldb + n0 + c];
            __nv_bfloat16 h = __float2bfloat16(v);
            Bhi[r * BNP + c] = h;
            Blo[r * BNP + c] = __float2bfloat16(v - __bfloat162float(h));
        }
        __syncthreads();

#pragma unroll
        for (int kf = 0; kf < BK / 16; kf++) {
            wmma::fragment<wmma::matrix_a, 16, 16, 16, __nv_bfloat16, wmma::row_major> ah[MFRAG], al[MFRAG];
#pragma unroll
            for (int mf = 0; mf < MFRAG; mf++) {
                const __nv_bfloat16* ap = &Ahi[(wm * WM + mf * 16) * BKP + kf * 16];
                wmma::load_matrix_sync(ah[mf], ap, BKP);
                wmma::load_matrix_sync(al[mf], &Alo[(wm * WM + mf * 16) * BKP + kf * 16], BKP);
            }
#pragma unroll
            for (int nf = 0; nf < NFRAG; nf++) {
                wmma::fragment<wmma::matrix_b, 16, 16, 16, __nv_bfloat16, wmma::row_major> bh, bl;
                wmma::load_matrix_sync(bh, &Bhi[(kf * 16) * BNP + wn * WN + nf * 16], BNP);
                wmma::load_matrix_sync(bl, &Blo[(kf * 16) * BNP + wn * WN + nf * 16], BNP);
#pragma unroll
                for (int mf = 0; mf < MFRAG; mf++) {
                    wmma::mma_sync(acc[mf][nf], ah[mf], bh, acc[mf][nf]);
                    wmma::mma_sync(acc[mf][nf], al[mf], bh, acc[mf][nf]);
                    wmma::mma_sync(acc[mf][nf], ah[mf], bl, acc[mf][nf]);
                }
            }
        }
    }

    // epilogue: bias (acc-layout fragment add), optional tanh, direct gmem store
#pragma unroll
    for (int nf = 0; nf < NFRAG; nf++) {
        wmma::fragment<wmma::accumulator, 16, 16, 16, float> bf;
        wmma::load_matrix_sync(bf, &biasT[wn * WN + nf * 16], BNPF, wmma::mem_row_major);
#pragma unroll
        for (int mf = 0; mf < MFRAG; mf++) {
#pragma unroll
            for (int e = 0; e < acc[mf][nf].num_elements; e++) {
                float v = acc[mf][nf].x[e] + bf.x[e];
                if (DOTANH) v = tanhf(v);
                acc[mf][nf].x[e] = v;
            }
            float* cp = C + (long)(rowBase + wm * WM + mf * 16) * ldc + n0 + wn * WN + nf * 16;
            wmma::store_matrix_sync(cp, acc[mf][nf], ldc, wmma::mem_row_major);
        }
    }
}

// ---------------- init: zero all per-launch accumulators ----------------
__global__ void init_kernel() {
    int t = threadIdx.x;
    for (int i = t; i < NCLS * NCONS; i += blockDim.x) g_msum[i] = 0.f;
    if (t < NCLS) { g_T[t] = 0.f; g_cnt[t] = 0; g_cur[t] = 0; }
    if (t == 0) g_cdiff = 0.f;
}

// ---------------- per-point / per-class statistics ----------------
__global__ void stats_kernel(const float* __restrict__ x) {
    __shared__ float sm[NCLS * NCONS];
    __shared__ float sT[NCLS];
    __shared__ int   sC[NCLS];
    int tid = threadIdx.x;
    for (int i = tid; i < NCLS * NCONS; i += blockDim.x) sm[i] = 0.f;
    if (tid < NCLS) { sT[tid] = 0.f; sC[tid] = 0; }
    __syncthreads();

    int i = blockIdx.x * blockDim.x + tid;       // exact coverage (32*256 = 8192)
    int l = (int)x[(long)i * (DIN + 1)];
    const float* e = g_emb + (long)i * EMBD + NEFF;
    float sq = 0.f;
#pragma unroll
    for (int d = 0; d < NCONS; d++) {
        float v = e[d];
        sq += v * v;
        atomicAdd(&sm[l * NCONS + d], v);
    }
    g_sq[i] = sq;
    g_lbl[i] = l;
    atomicAdd(&sT[l], sq);
    atomicAdd(&sC[l], 1);
    __syncthreads();

    for (int j = tid; j < NCLS * NCONS; j += blockDim.x) atomicAdd(&g_msum[j], sm[j]);
    if (tid < NCLS) {
        atomicAdd(&g_T[tid], sT[tid]);
        atomicAdd(&g_cnt[tid], sC[tid]);
    }
}

// ---------------- counting-sort offsets + tile offsets ----------------
__global__ void offsets_kernel() {
    if (threadIdx.x == 0 && blockIdx.x == 0) {
        int acc = 0, tacc = 0;
        for (int k = 0; k < NCLS; k++) {
            g_off[k] = acc; acc += g_cnt[k];
            g_cur[k] = 0;
            int t = (g_cnt[k] + 31) >> 5;
            g_tileoff[k] = tacc; tacc += t * t;
        }
        g_off[NCLS] = acc;
        g_tileoff[NCLS] = tacc;
    }
}

__global__ void scatter_kernel() {
    int i = blockIdx.x * blockDim.x + threadIdx.x;
    int l = g_lbl[i];
    int pos = g_off[l] + atomicAdd(&g_cur[l], 1);
    g_perm[pos] = i;
}

// ---------------- same-class pairwise C_diff (persistent tile loop) ----------------
__global__ __launch_bounds__(256)
void pairwise_kernel() {
    __shared__ float Ci[32][NCONS + 1];   // pad to 63: conflict-free
    __shared__ float Cj[32][NCONS + 1];
    __shared__ float sqi[32], sqj[32];
    __shared__ float red[256];

    int tid = threadIdx.x;
    int total = g_tileoff[NCLS];
    float accT = 0.f;

    for (int w = blockIdx.x; w < total; w += gridDim.x) {
        int k = 0;
        while (g_tileoff[k + 1] <= w) k++;
        int n = g_cnt[k];
        int tpd = (n + 31) >> 5;
        int local = w - g_tileoff[k];
        int ti = local / tpd, tj = local % tpd;
        int base = g_off[k];
        int ni = min(32, n - ti * 32);
        int nj = min(32, n - tj * 32);

        __syncthreads();   // protect shared reuse across tiles
        for (int idx = tid; idx < 32 * NCONS; idx += blockDim.x) {
            int r = idx / NCONS, d = idx % NCONS;
            int a = ti * 32 + r;
            if (a < n) {
                int gi = g_perm[base + a];
                Ci[r][d] = g_emb[(long)gi * EMBD + NEFF + d];
                if (d == 0) sqi[r] = g_sq[gi];
            }
            int b = tj * 32 + r;
            if (b < n) {
                int gj = g_perm[base + b];
                Cj[r][d] = g_emb[(long)gj * EMBD + NEFF + d];
                if (d == 0) sqj[r] = g_sq[gj];
            }
        }
        __syncthreads();

        int b = tid & 31;        // varies across warp -> conflict-free Cj reads
        int a0 = tid >> 5;       // uniform across warp -> broadcast Ci reads
        if (b < nj) {
            float sj = sqj[b];
#pragma unroll
            for (int m = 0; m < 4; m++) {
                int a = a0 + m * 8;
                if (a < ni) {
                    float dot = 0.f;
#pragma unroll
                    for (int d = 0; d < NCONS; d++) dot += Ci[a][d] * Cj[b][d];
                    float D = fmaxf(sqi[a] + sj - 2.f * dot, 0.f) * (1.f / NCONS);
                    float t = MARGIN - D;
                    if (t > 0.f) accT += t;
                }
            }
        }
    }

    red[tid] = accT;
    __syncthreads();
    for (int s = 128; s > 0; s >>= 1) {
        if (tid < s) red[tid] += red[tid + s];
        __syncthreads();
    }
    if (tid == 0 && red[0] != 0.f) atomicAdd(&g_cdiff, red[0]);
}

// ---------------- finalize: closed-form C_sim, normalize C_diff ----------------
__global__ void finalize_kernel(float* __restrict__ out) {
    if (threadIdx.x != 0 || blockIdx.x != 0) return;
    float M[NCONS];
#pragma unroll
    for (int d = 0; d < NCONS; d++) M[d] = 0.f;
    float sumTw = 0.f, summ2 = 0.f;
    long long sumn2 = 0;
    for (int k = 0; k < NCLS; k++) {
        int n = g_cnt[k];
        sumn2 += (long long)n * n;
        sumTw += g_T[k] * (float)(NPTS - n);
        float mm = 0.f;
        for (int d = 0; d < NCONS; d++) {
            float v = g_msum[k * NCONS + d];
            M[d] += v;
            mm += v * v;
        }
        summ2 += mm;
    }
    float MM = 0.f;
    for (int d = 0; d < NCONS; d++) MM += M[d] * M[d];

    double ndiff = (double)NPTS * (double)NPTS - (double)sumn2;
    float raw = 2.f * sumTw - 2.f * (MM - summ2);
    float csim = raw * (1.f / NCONS) / (float)(ndiff + 1.0);
    float cdiff = g_cdiff / (float)((double)NPTS * (double)NPTS - ndiff + 1.0);

    out[(long)NPTS * DIN]     = csim;
    out[(long)NPTS * DIN + 1] = cdiff;
}

// ---------------- launch ----------------
extern "C" void kernel_launch(void* const* d_in, const int* in_sizes, int n_in,
                              void* d_out, int out_size) {
    const float* x  = (const float*)d_in[0];
    const float* W1 = (const float*)d_in[1];
    const float* b1 = (const float*)d_in[2];
    const float* W2 = (const float*)d_in[3];
    const float* b2 = (const float*)d_in[4];
    const float* W3 = (const float*)d_in[5];
    const float* b3 = (const float*)d_in[6];
    const float* W4 = (const float*)d_in[7];
    const float* b4 = (const float*)d_in[8];
    float* out = (float*)d_out;

    void *p_h1, *p_emb, *p_h2;
    cudaGetSymbolAddress(&p_h1,  g_h1);
    cudaGetSymbolAddress(&p_emb, g_emb);
    cudaGetSymbolAddress(&p_h2,  g_h2);
    float* h1  = (float*)p_h1;
    float* emb = (float*)p_emb;
    float* h2  = (float*)p_h2;

    init_kernel<<<1, 256>>>();

    // h1 = tanh(data @ W1 + b1)   data = x[:,1:], lda = 513
    {
        dim3 grid(HID / 128, NPTS / 128);
        hgemm<128, 128, 32, 64, true><<<grid, 256>>>(x + 1, DIN + 1, W1, HID, b1, h1, HID, DIN);
    }
    // emb = h1 @ W2 + b2  (N = 64: 64x64 tiles -> 128 blocks)
    {
        dim3 grid(EMBD / 64, NPTS / 64);
        hgemm<64, 64, 16, 32, false><<<grid, 256>>>(h1, HID, W2, EMBD, b2, emb, EMBD, HID);
    }
    // h2 = tanh(emb @ W3 + b3)
    {
        dim3 grid(HID / 128, NPTS / 128);
        hgemm<128, 128, 32, 64, true><<<grid, 256>>>(emb, EMBD, W3, HID, b3, h2, HID, EMBD);
    }
    // decoded = h2 @ W4 + b4  -> first NPTS*DIN floats of out
    {
        dim3 grid(DIN / 128, NPTS / 128);
        hgemm<128, 128, 32, 64, false><<<grid, 256>>>(h2, HID, W4, DIN, b4, out, DIN, HID);
    }

    stats_kernel<<<NPTS / 256, 256>>>(x);
    offsets_kernel<<<1, 32>>>();
    scatter_kernel<<<NPTS / 256, 256>>>();
    pairwise_kernel<<<4096, 256>>>();
    finalize_kernel<<<1, 32>>>(out);
}

// round 5
// speedup vs baseline: 1.9700x; 1.3468x over previous
#include <cuda_runtime.h>
#include <cuda_bf16.h>
#include <mma.h>
#include <math.h>
#include <stdint.h>

using namespace nvcuda;

#define NPTS 8192
#define DIN  512
#define HID  1024
#define EMBD 64
#define NEFF 2
#define NCONS 62   // EMBD - NEFF
#define NCLS 16
#define MARGIN 0.01f

// ---------------- scratch (static device globals; no allocation) ----------------
__device__ __nv_bfloat16 g_xhi[NPTS * DIN],  g_xlo[NPTS * DIN];
__device__ __nv_bfloat16 g_w1hi[DIN * HID],  g_w1lo[DIN * HID];
__device__ __nv_bfloat16 g_w2hi[HID * EMBD], g_w2lo[HID * EMBD];
__device__ __nv_bfloat16 g_w3hi[EMBD * HID], g_w3lo[EMBD * HID];
__device__ __nv_bfloat16 g_w4hi[HID * DIN],  g_w4lo[HID * DIN];
__device__ __nv_bfloat16 g_h1hi[NPTS * HID], g_h1lo[NPTS * HID];
__device__ __nv_bfloat16 g_h2hi[NPTS * HID], g_h2lo[NPTS * HID];
__device__ __nv_bfloat16 g_ehi[NPTS * EMBD], g_elo[NPTS * EMBD];
__device__ float g_emb[NPTS * EMBD];
__device__ float g_sq[NPTS];
__device__ int   g_lbl[NPTS];
__device__ int   g_cnt[NCLS];
__device__ int   g_off[NCLS + 1];
__device__ int   g_cur[NCLS];
__device__ int   g_perm[NPTS];
__device__ int   g_tileoff[NCLS + 1];
__device__ float g_msum[NCLS * NCONS];
__device__ float g_T[NCLS];
__device__ float g_cdiff;

__device__ __forceinline__ uint32_t pack_bf2(__nv_bfloat16 a, __nv_bfloat16 b) {
    __nv_bfloat162 t = __halves2bfloat162(a, b);
    return *reinterpret_cast<uint32_t*>(&t);
}

// ---------------- pre-split kernels ----------------
__global__ void split_x_kernel(const float* __restrict__ x) {
    int idx = blockIdx.x * 256 + threadIdx.x;          // exact: NPTS*DIN / 256 blocks
    int r = idx / DIN, c = idx % DIN;
    float v = x[(long)r * (DIN + 1) + 1 + c];
    __nv_bfloat16 h = __float2bfloat16(v);
    g_xhi[idx] = h;
    g_xlo[idx] = __float2bfloat16(v - __bfloat162float(h));
}

__global__ void split_w_kernel(const float* __restrict__ W,
                               __nv_bfloat16* __restrict__ hi,
                               __nv_bfloat16* __restrict__ lo, int n) {
    int idx = blockIdx.x * 256 + threadIdx.x;
    if (idx >= n) return;
    float v = W[idx];
    __nv_bfloat16 h = __float2bfloat16(v);
    hi[idx] = h;
    lo[idx] = __float2bfloat16(v - __bfloat162float(h));
}

// ================= WMMA bf16 split GEMM, pre-split operands =================
// OUTMODE: 0 = fp32 only, 1 = split bf16 only, 2 = both.
template<int BM, int BN, int WM, int WN, int OUTMODE, bool DOTANH>
__global__ __launch_bounds__(256, 2)
void hgemm_pre(const __nv_bfloat16* __restrict__ Ahi_g, const __nv_bfloat16* __restrict__ Alo_g,
               const __nv_bfloat16* __restrict__ Bhi_g, const __nv_bfloat16* __restrict__ Blo_g,
               const float* __restrict__ bias,
               float* __restrict__ C, __nv_bfloat16* __restrict__ Chi,
               __nv_bfloat16* __restrict__ Clo, int K, int N)
{
    constexpr int BK = 32, BKP = 40, BNP = BN + 8;
    constexpr int MW = BM / WM, NW = BN / WN;
    static_assert(MW * NW == 8, "8 warps");
    constexpr int MFRAG = WM / 16, NFRAG = WN / 16;
    constexpr int A_ELEMS = BM * BKP, B_ELEMS = BK * BNP;
    constexpr int TILE_BYTES = 2 * (A_ELEMS + B_ELEMS) * 2;
    constexpr int STAGE_BYTES = 8 * 16 * 20 * 4;
    constexpr int SMEM_BYTES = TILE_BYTES > STAGE_BYTES ? TILE_BYTES : STAGE_BYTES;

    __shared__ __align__(16) unsigned char sraw[SMEM_BYTES];
    __nv_bfloat16* Ahi = (__nv_bfloat16*)sraw;
    __nv_bfloat16* Alo = Ahi + A_ELEMS;
    __nv_bfloat16* Bhi = Alo + A_ELEMS;
    __nv_bfloat16* Blo = Bhi + B_ELEMS;
    float* stage = (float*)sraw;                 // overlays tiles (dead in epilogue)

    const int tid = threadIdx.x;
    const int wid = tid >> 5, lid = tid & 31;
    const int wm = wid % MW, wn = wid / MW;
    const int rowBase = blockIdx.y * BM;
    const int n0 = blockIdx.x * BN;

    wmma::fragment<wmma::accumulator, 16, 16, 16, float> acc[MFRAG][NFRAG];
#pragma unroll
    for (int mf = 0; mf < MFRAG; mf++)
#pragma unroll
        for (int nf = 0; nf < NFRAG; nf++)
            wmma::fill_fragment(acc[mf][nf], 0.0f);

    const int nChunks = K / BK;
    for (int ch = 0; ch < nChunks; ch++) {
        const int k0 = ch * BK;
        __syncthreads();

        constexpr int AU = BM * BK / 8;          // uint4 per A buffer
#pragma unroll
        for (int i = tid; i < AU; i += 256) {
            int r = i >> 2, c8 = (i & 3) << 3;
            long src = (long)(rowBase + r) * K + k0 + c8;
            int dst = r * BKP + c8;
            *(uint4*)&Ahi[dst] = *(const uint4*)&Ahi_g[src];
            *(uint4*)&Alo[dst] = *(const uint4*)&Alo_g[src];
        }
        constexpr int BU = BK * BN / 8;
        constexpr int BROW = BN / 8;
#pragma unroll
        for (int i = tid; i < BU; i += 256) {
            int r = i / BROW, c8 = (i % BROW) << 3;
            long src = (long)(k0 + r) * N + n0 + c8;
            int dst = r * BNP + c8;
            *(uint4*)&Bhi[dst] = *(const uint4*)&Bhi_g[src];
            *(uint4*)&Blo[dst] = *(const uint4*)&Blo_g[src];
        }
        __syncthreads();

#pragma unroll
        for (int kf = 0; kf < BK / 16; kf++) {
            wmma::fragment<wmma::matrix_a, 16, 16, 16, __nv_bfloat16, wmma::row_major> ah[MFRAG], al[MFRAG];
#pragma unroll
            for (int mf = 0; mf < MFRAG; mf++) {
                wmma::load_matrix_sync(ah[mf], &Ahi[(wm * WM + mf * 16) * BKP + kf * 16], BKP);
                wmma::load_matrix_sync(al[mf], &Alo[(wm * WM + mf * 16) * BKP + kf * 16], BKP);
            }
#pragma unroll
            for (int nf = 0; nf < NFRAG; nf++) {
                wmma::fragment<wmma::matrix_b, 16, 16, 16, __nv_bfloat16, wmma::row_major> bh, bl;
                wmma::load_matrix_sync(bh, &Bhi[(kf * 16) * BNP + wn * WN + nf * 16], BNP);
                wmma::load_matrix_sync(bl, &Blo[(kf * 16) * BNP + wn * WN + nf * 16], BNP);
#pragma unroll
                for (int mf = 0; mf < MFRAG; mf++) {
                    wmma::mma_sync(acc[mf][nf], ah[mf], bh, acc[mf][nf]);
                    wmma::mma_sync(acc[mf][nf], al[mf], bh, acc[mf][nf]);
                    wmma::mma_sync(acc[mf][nf], ah[mf], bl, acc[mf][nf]);
                }
            }
        }
    }

    // ---- epilogue via per-warp smem staging ----
    __syncthreads();
    float* wstage = stage + wid * (16 * 20);
#pragma unroll
    for (int mf = 0; mf < MFRAG; mf++) {
#pragma unroll
        for (int nf = 0; nf < NFRAG; nf++) {
            wmma::store_matrix_sync(wstage, acc[mf][nf], 20, wmma::mem_row_major);
            __syncwarp();
            int r = lid >> 1, c0 = (lid & 1) << 3;
            long grow = rowBase + wm * WM + mf * 16 + r;
            int gcol = n0 + wn * WN + nf * 16 + c0;
            const float4* bp = (const float4*)&bias[gcol];
            float4 b0 = bp[0], b1 = bp[1];
            float v[8];
            v[0] = wstage[r * 20 + c0 + 0] + b0.x;
            v[1] = wstage[r * 20 + c0 + 1] + b0.y;
            v[2] = wstage[r * 20 + c0 + 2] + b0.z;
            v[3] = wstage[r * 20 + c0 + 3] + b0.w;
            v[4] = wstage[r * 20 + c0 + 4] + b1.x;
            v[5] = wstage[r * 20 + c0 + 5] + b1.y;
            v[6] = wstage[r * 20 + c0 + 6] + b1.z;
            v[7] = wstage[r * 20 + c0 + 7] + b1.w;
            if (DOTANH) {
#pragma unroll
                for (int j = 0; j < 8; j++) v[j] = tanhf(v[j]);
            }
            if (OUTMODE != 1) {
                float4* cp = (float4*)&C[grow * N + gcol];
                cp[0] = make_float4(v[0], v[1], v[2], v[3]);
                cp[1] = make_float4(v[4], v[5], v[6], v[7]);
            }
            if (OUTMODE >= 1) {
                __nv_bfloat16 h[8];
                uint4 uh, ul;
#pragma unroll
                for (int j = 0; j < 8; j++) h[j] = __float2bfloat16(v[j]);
                uh.x = pack_bf2(h[0], h[1]); uh.y = pack_bf2(h[2], h[3]);
                uh.z = pack_bf2(h[4], h[5]); uh.w = pack_bf2(h[6], h[7]);
                __nv_bfloat16 l[8];
#pragma unroll
                for (int j = 0; j < 8; j++)
                    l[j] = __float2bfloat16(v[j] - __bfloat162float(h[j]));
                ul.x = pack_bf2(l[0], l[1]); ul.y = pack_bf2(l[2], l[3]);
                ul.z = pack_bf2(l[4], l[5]); ul.w = pack_bf2(l[6], l[7]);
                *(uint4*)&Chi[grow * N + gcol] = uh;
                *(uint4*)&Clo[grow * N + gcol] = ul;
            }
            __syncwarp();
        }
    }
}

// ---------------- init: zero all per-launch accumulators ----------------
__global__ void init_kernel() {
    int t = threadIdx.x;
    for (int i = t; i < NCLS * NCONS; i += blockDim.x) g_msum[i] = 0.f;
    if (t < NCLS) { g_T[t] = 0.f; g_cnt[t] = 0; g_cur[t] = 0; }
    if (t == 0) g_cdiff = 0.f;
}

// ---------------- per-point / per-class statistics ----------------
__global__ void stats_kernel(const float* __restrict__ x) {
    __shared__ float sm[NCLS * NCONS];
    __shared__ float sT[NCLS];
    __shared__ int   sC[NCLS];
    int tid = threadIdx.x;
    for (int i = tid; i < NCLS * NCONS; i += blockDim.x) sm[i] = 0.f;
    if (tid < NCLS) { sT[tid] = 0.f; sC[tid] = 0; }
    __syncthreads();

    int i = blockIdx.x * blockDim.x + tid;       // exact coverage (32*256 = 8192)
    int l = (int)x[(long)i * (DIN + 1)];
    const float* e = g_emb + (long)i * EMBD + NEFF;
    float sq = 0.f;
#pragma unroll
    for (int d = 0; d < NCONS; d++) {
        float v = e[d];
        sq += v * v;
        atomicAdd(&sm[l * NCONS + d], v);
    }
    g_sq[i] = sq;
    g_lbl[i] = l;
    atomicAdd(&sT[l], sq);
    atomicAdd(&sC[l], 1);
    __syncthreads();

    for (int j = tid; j < NCLS * NCONS; j += blockDim.x) atomicAdd(&g_msum[j], sm[j]);
    if (tid < NCLS) {
        atomicAdd(&g_T[tid], sT[tid]);
        atomicAdd(&g_cnt[tid], sC[tid]);
    }
}

// ---------------- counting-sort offsets + tile offsets ----------------
__global__ void offsets_kernel() {
    if (threadIdx.x == 0 && blockIdx.x == 0) {
        int acc = 0, tacc = 0;
        for (int k = 0; k < NCLS; k++) {
            g_off[k] = acc; acc += g_cnt[k];
            g_cur[k] = 0;
            int t = (g_cnt[k] + 31) >> 5;
            g_tileoff[k] = tacc; tacc += t * t;
        }
        g_off[NCLS] = acc;
        g_tileoff[NCLS] = tacc;
    }
}

__global__ void scatter_kernel() {
    int i = blockIdx.x * blockDim.x + threadIdx.x;
    int l = g_lbl[i];
    int pos = g_off[l] + atomicAdd(&g_cur[l], 1);
    g_perm[pos] = i;
}

// ---------------- same-class pairwise C_diff (persistent tile loop) ----------------
__global__ __launch_bounds__(256)
void pairwise_kernel() {
    __shared__ float Ci[32][NCONS + 1];   // pad to 63: conflict-free
    __shared__ float Cj[32][NCONS + 1];
    __shared__ float sqi[32], sqj[32];
    __shared__ float red[256];

    int tid = threadIdx.x;
    int total = g_tileoff[NCLS];
    float accT = 0.f;

    for (int w = blockIdx.x; w < total; w += gridDim.x) {
        int k = 0;
        while (g_tileoff[k + 1] <= w) k++;
        int n = g_cnt[k];
        int tpd = (n + 31) >> 5;
        int local = w - g_tileoff[k];
        int ti = local / tpd, tj = local % tpd;
        int base = g_off[k];
        int ni = min(32, n - ti * 32);
        int nj = min(32, n - tj * 32);

        __syncthreads();   // protect shared reuse across tiles
        for (int idx = tid; idx < 32 * NCONS; idx += blockDim.x) {
            int r = idx / NCONS, d = idx % NCONS;
            int a = ti * 32 + r;
            if (a < n) {
                int gi = g_perm[base + a];
                Ci[r][d] = g_emb[(long)gi * EMBD + NEFF + d];
                if (d == 0) sqi[r] = g_sq[gi];
            }
            int b = tj * 32 + r;
            if (b < n) {
                int gj = g_perm[base + b];
                Cj[r][d] = g_emb[(long)gj * EMBD + NEFF + d];
                if (d == 0) sqj[r] = g_sq[gj];
            }
        }
        __syncthreads();

        int b = tid & 31;        // varies across warp -> conflict-free Cj reads
        int a0 = tid >> 5;       // uniform across warp -> broadcast Ci reads
        if (b < nj) {
            float sj = sqj[b];
#pragma unroll
            for (int m = 0; m < 4; m++) {
                int a = a0 + m * 8;
                if (a < ni) {
                    float dot = 0.f;
#pragma unroll
                    for (int d = 0; d < NCONS; d++) dot += Ci[a][d] * Cj[b][d];
                    float D = fmaxf(sqi[a] + sj - 2.f * dot, 0.f) * (1.f / NCONS);
                    float t = MARGIN - D;
                    if (t > 0.f) accT += t;
                }
            }
        }
    }

    red[tid] = accT;
    __syncthreads();
    for (int s = 128; s > 0; s >>= 1) {
        if (tid < s) red[tid] += red[tid + s];
        __syncthreads();
    }
    if (tid == 0 && red[0] != 0.f) atomicAdd(&g_cdiff, red[0]);
}

// ---------------- finalize: parallel closed-form C_sim, normalize C_diff ----------------
__global__ void finalize_kernel(float* __restrict__ out) {
    __shared__ float Msh[NCONS];
    __shared__ float s_summ2, s_sumTw, s_MM;
    __shared__ unsigned long long s_n2;
    int tid = threadIdx.x;
    if (tid < NCONS) Msh[tid] = 0.f;
    if (tid == 0) { s_summ2 = 0.f; s_sumTw = 0.f; s_MM = 0.f; s_n2 = 0ull; }
    __syncthreads();

    float p2 = 0.f;
    for (int i = tid; i < NCLS * NCONS; i += blockDim.x) {
        float v = g_msum[i];
        p2 += v * v;
        atomicAdd(&Msh[i % NCONS], v);
    }
    if (p2 != 0.f) atomicAdd(&s_summ2, p2);
    if (tid < NCLS) {
        int n = g_cnt[tid];
        atomicAdd(&s_n2, (unsigned long long)n * (unsigned long long)n);
        atomicAdd(&s_sumTw, g_T[tid] * (float)(NPTS - n));
    }
    __syncthreads();
    if (tid < NCONS) atomicAdd(&s_MM, Msh[tid] * Msh[tid]);
    __syncthreads();

    if (tid == 0) {
        double ndiff = (double)NPTS * (double)NPTS - (double)s_n2;
        float raw = 2.f * s_sumTw - 2.f * (s_MM - s_summ2);
        float csim = raw * (1.f / NCONS) / (float)(ndiff + 1.0);
        float cdiff = g_cdiff / (float)((double)NPTS * (double)NPTS - ndiff + 1.0);
        out[(long)NPTS * DIN]     = csim;
        out[(long)NPTS * DIN + 1] = cdiff;
    }
}

// ---------------- launch ----------------
extern "C" void kernel_launch(void* const* d_in, const int* in_sizes, int n_in,
                              void* d_out, int out_size) {
    const float* x  = (const float*)d_in[0];
    const float* W1 = (const float*)d_in[1];
    const float* b1 = (const float*)d_in[2];
    const float* W2 = (const float*)d_in[3];
    const float* b2 = (const float*)d_in[4];
    const float* W3 = (const float*)d_in[5];
    const float* b3 = (const float*)d_in[6];
    const float* W4 = (const float*)d_in[7];
    const float* b4 = (const float*)d_in[8];
    float* out = (float*)d_out;

    // resolve device-global scratch addresses
    void *pxh, *pxl, *p1h, *p1l, *p2h, *p2l, *p3h, *p3l, *p4h, *p4l;
    void *ph1h, *ph1l, *ph2h, *ph2l, *peh, *pel, *pemb;
    cudaGetSymbolAddress(&pxh, g_xhi);   cudaGetSymbolAddress(&pxl, g_xlo);
    cudaGetSymbolAddress(&p1h, g_w1hi);  cudaGetSymbolAddress(&p1l, g_w1lo);
    cudaGetSymbolAddress(&p2h, g_w2hi);  cudaGetSymbolAddress(&p2l, g_w2lo);
    cudaGetSymbolAddress(&p3h, g_w3hi);  cudaGetSymbolAddress(&p3l, g_w3lo);
    cudaGetSymbolAddress(&p4h, g_w4hi);  cudaGetSymbolAddress(&p4l, g_w4lo);
    cudaGetSymbolAddress(&ph1h, g_h1hi); cudaGetSymbolAddress(&ph1l, g_h1lo);
    cudaGetSymbolAddress(&ph2h, g_h2hi); cudaGetSymbolAddress(&ph2l, g_h2lo);
    cudaGetSymbolAddress(&peh, g_ehi);   cudaGetSymbolAddress(&pel, g_elo);
    cudaGetSymbolAddress(&pemb, g_emb);
    typedef __nv_bfloat16 bf;

    init_kernel<<<1, 256>>>();

    // pre-split inputs
    split_x_kernel<<<NPTS * DIN / 256, 256>>>(x);
    split_w_kernel<<<DIN * HID / 256, 256>>>(W1, (bf*)p1h, (bf*)p1l, DIN * HID);
    split_w_kernel<<<HID * EMBD / 256, 256>>>(W2, (bf*)p2h, (bf*)p2l, HID * EMBD);
    split_w_kernel<<<EMBD * HID / 256, 256>>>(W3, (bf*)p3h, (bf*)p3l, EMBD * HID);
    split_w_kernel<<<HID * DIN / 256, 256>>>(W4, (bf*)p4h, (bf*)p4l, HID * DIN);

    // h1 = tanh(data @ W1 + b1) -> split bf16 only
    {
        dim3 grid(HID / 128, NPTS / 128);
        hgemm_pre<128, 128, 32, 64, 1, true><<<grid, 256>>>(
            (bf*)pxh, (bf*)pxl, (bf*)p1h, (bf*)p1l, b1,
            nullptr, (bf*)ph1h, (bf*)ph1l, DIN, HID);
    }
    // emb = h1 @ W2 + b2 -> fp32 + split
    {
        dim3 grid(EMBD / 64, NPTS / 64);
        hgemm_pre<64, 64, 16, 32, 2, false><<<grid, 256>>>(
            (bf*)ph1h, (bf*)ph1l, (bf*)p2h, (bf*)p2l, b2,
            (float*)pemb, (bf*)peh, (bf*)pel, HID, EMBD);
    }
    // h2 = tanh(emb @ W3 + b3) -> split bf16 only
    {
        dim3 grid(HID / 128, NPTS / 128);
        hgemm_pre<128, 128, 32, 64, 1, true><<<grid, 256>>>(
            (bf*)peh, (bf*)pel, (bf*)p3h, (bf*)p3l, b3,
            nullptr, (bf*)ph2h, (bf*)ph2l, EMBD, HID);
    }
    // decoded = h2 @ W4 + b4 -> fp32 out
    {
        dim3 grid(DIN / 128, NPTS / 128);
        hgemm_pre<128, 128, 32, 64, 0, false><<<grid, 256>>>(
            (bf*)ph2h, (bf*)ph2l, (bf*)p4h, (bf*)p4l, b4,
            out, nullptr, nullptr, HID, DIN);
    }

    stats_kernel<<<NPTS / 256, 256>>>(x);
    offsets_kernel<<<1, 32>>>();
    scatter_kernel<<<NPTS / 256, 256>>>();
    pairwise_kernel<<<4096, 256>>>();
    finalize_kernel<<<1, 256>>>(out);
}

// round 11
// speedup vs baseline: 2.2314x; 1.1327x over previous
#include <cuda_runtime.h>
#include <cuda_bf16.h>
#include <cuda_pipeline.h>
#include <mma.h>
#include <math.h>
#include <stdint.h>

using namespace nvcuda;

#define NPTS 8192
#define DIN  512
#define HID  1024
#define EMBD 64
#define NEFF 2
#define NCONS 62   // EMBD - NEFF
#define NCLS 16
#define MARGIN 0.01f

// ---------------- scratch (static device globals; no allocation) ----------------
__device__ __nv_bfloat16 g_xhi[NPTS * DIN],  g_xlo[NPTS * DIN];
__device__ __nv_bfloat16 g_w1hi[DIN * HID],  g_w1lo[DIN * HID];
__device__ __nv_bfloat16 g_w2hi[HID * EMBD], g_w2lo[HID * EMBD];
__device__ __nv_bfloat16 g_w3hi[EMBD * HID], g_w3lo[EMBD * HID];
__device__ __nv_bfloat16 g_w4hi[HID * DIN],  g_w4lo[HID * DIN];
__device__ __nv_bfloat16 g_h1hi[NPTS * HID], g_h1lo[NPTS * HID];
__device__ __nv_bfloat16 g_h2hi[NPTS * HID], g_h2lo[NPTS * HID];
__device__ __nv_bfloat16 g_ehi[NPTS * EMBD], g_elo[NPTS * EMBD];
__device__ float g_emb[NPTS * EMBD];
__device__ float g_sq[NPTS];
__device__ int   g_lbl[NPTS];
__device__ int   g_cnt[NCLS];
__device__ int   g_off[NCLS + 1];
__device__ int   g_cur[NCLS];
__device__ int   g_perm[NPTS];
__device__ int   g_tileoff[NCLS + 1];
__device__ float g_msum[NCLS * NCONS];
__device__ float g_T[NCLS];
__device__ float g_cdiff;

__device__ __forceinline__ uint32_t pack_bf2(__nv_bfloat16 a, __nv_bfloat16 b) {
    __nv_bfloat162 t = __halves2bfloat162(a, b);
    return *reinterpret_cast<uint32_t*>(&t);
}

// ---------------- pre-split kernels ----------------
__global__ void split_x_kernel(const float* __restrict__ x) {
    int idx = blockIdx.x * 256 + threadIdx.x;          // exact: NPTS*DIN / 256 blocks
    int r = idx / DIN, c = idx % DIN;
    float v = x[(long)r * (DIN + 1) + 1 + c];
    __nv_bfloat16 h = __float2bfloat16(v);
    g_xhi[idx] = h;
    g_xlo[idx] = __float2bfloat16(v - __bfloat162float(h));
}

__global__ void split_w_kernel(const float* __restrict__ W,
                               __nv_bfloat16* __restrict__ hi,
                               __nv_bfloat16* __restrict__ lo, int n) {
    int idx = blockIdx.x * 256 + threadIdx.x;
    if (idx >= n) return;
    float v = W[idx];
    __nv_bfloat16 h = __float2bfloat16(v);
    hi[idx] = h;
    lo[idx] = __float2bfloat16(v - __bfloat162float(h));
}

// ================= WMMA bf16 split GEMM, cp.async 2-stage pipeline =================
// OUTMODE: 0 = fp32 only, 1 = split bf16 only, 2 = both.
template<int BM, int BN, int WM, int WN, int OUTMODE, bool DOTANH>
__global__ __launch_bounds__(256, 2)
void hgemm_cp(const __nv_bfloat16* __restrict__ Ahi_g, const __nv_bfloat16* __restrict__ Alo_g,
              const __nv_bfloat16* __restrict__ Bhi_g, const __nv_bfloat16* __restrict__ Blo_g,
              const float* __restrict__ bias,
              float* __restrict__ C, __nv_bfloat16* __restrict__ Chi,
              __nv_bfloat16* __restrict__ Clo, int K, int N)
{
    constexpr int BK = 32, BKP = 40, BNP = BN + 8;
    constexpr int MW = BM / WM, NW = BN / WN;
    static_assert(MW * NW == 8, "8 warps");
    constexpr int MFRAG = WM / 16, NFRAG = WN / 16;
    constexpr int A_EL = BM * BKP;                 // bf16 elems per A buffer
    constexpr int B_EL = BK * BNP;
    constexpr int STAGE_EL = 2 * A_EL + 2 * B_EL;  // hi+lo for A and B

    extern __shared__ __align__(16) unsigned char dsm[];
    __nv_bfloat16* sbase = (__nv_bfloat16*)dsm;
    float* stage_epi = (float*)dsm;                // overlays tiles (dead in epilogue)

    const int tid = threadIdx.x;
    const int wid = tid >> 5, lid = tid & 31;
    const int wm = wid % MW, wn = wid / MW;
    const int rowBase = blockIdx.y * BM;
    const int n0 = blockIdx.x * BN;

    // per-stage tile pointers
    auto AhiS = [&](int s) { return sbase + s * STAGE_EL; };
    auto AloS = [&](int s) { return sbase + s * STAGE_EL + A_EL; };
    auto BhiS = [&](int s) { return sbase + s * STAGE_EL + 2 * A_EL; };
    auto BloS = [&](int s) { return sbase + s * STAGE_EL + 2 * A_EL + B_EL; };

    // async stage loader: pure 16B copies (warp-uniform control flow)
    auto load_stage = [&](int s, int ch) {
        const int k0 = ch * BK;
        __nv_bfloat16* ah = AhiS(s);
        __nv_bfloat16* al = AloS(s);
        __nv_bfloat16* bh = BhiS(s);
        __nv_bfloat16* bl = BloS(s);
        constexpr int AU = BM * BK / 8;            // uint4 count per A buffer
#pragma unroll
        for (int i = tid; i < AU; i += 256) {
            int r = i >> 2, c8 = (i & 3) << 3;
            long src = (long)(rowBase + r) * K + k0 + c8;
            int dst = r * BKP + c8;
            __pipeline_memcpy_async(&ah[dst], &Ahi_g[src], 16);
            __pipeline_memcpy_async(&al[dst], &Alo_g[src], 16);
        }
        constexpr int BU = BK * BN / 8;
        constexpr int BROW = BN / 8;
#pragma unroll
        for (int i = tid; i < BU; i += 256) {
            int r = i / BROW, c8 = (i % BROW) << 3;
            long src = (long)(k0 + r) * N + n0 + c8;
            int dst = r * BNP + c8;
            __pipeline_memcpy_async(&bh[dst], &Bhi_g[src], 16);
            __pipeline_memcpy_async(&bl[dst], &Blo_g[src], 16);
        }
        __pipeline_commit();
    };

    wmma::fragment<wmma::accumulator, 16, 16, 16, float> acc[MFRAG][NFRAG];
#pragma unroll
    for (int mf = 0; mf < MFRAG; mf++)
#pragma unroll
        for (int nf = 0; nf < NFRAG; nf++)
            wmma::fill_fragment(acc[mf][nf], 0.0f);

    const int nChunks = K / BK;
    load_stage(0, 0);

    for (int ch = 0; ch < nChunks; ch++) {
        const int buf = ch & 1;
        if (ch + 1 < nChunks) {
            load_stage(buf ^ 1, ch + 1);
            __pipeline_wait_prior(1);              // stage ch complete
        } else {
            __pipeline_wait_prior(0);
        }
        __syncthreads();

        const __nv_bfloat16* Ahi = AhiS(buf);
        const __nv_bfloat16* Alo = AloS(buf);
        const __nv_bfloat16* Bhi = BhiS(buf);
        const __nv_bfloat16* Blo = BloS(buf);

#pragma unroll
        for (int kf = 0; kf < BK / 16; kf++) {
            wmma::fragment<wmma::matrix_a, 16, 16, 16, __nv_bfloat16, wmma::row_major> ah[MFRAG], al[MFRAG];
#pragma unroll
            for (int mf = 0; mf < MFRAG; mf++) {
                wmma::load_matrix_sync(ah[mf], &Ahi[(wm * WM + mf * 16) * BKP + kf * 16], BKP);
                wmma::load_matrix_sync(al[mf], &Alo[(wm * WM + mf * 16) * BKP + kf * 16], BKP);
            }
#pragma unroll
            for (int nf = 0; nf < NFRAG; nf++) {
                wmma::fragment<wmma::matrix_b, 16, 16, 16, __nv_bfloat16, wmma::row_major> bh, bl;
                wmma::load_matrix_sync(bh, &Bhi[(kf * 16) * BNP + wn * WN + nf * 16], BNP);
                wmma::load_matrix_sync(bl, &Blo[(kf * 16) * BNP + wn * WN + nf * 16], BNP);
#pragma unroll
                for (int mf = 0; mf < MFRAG; mf++) {
                    wmma::mma_sync(acc[mf][nf], ah[mf], bh, acc[mf][nf]);
                    wmma::mma_sync(acc[mf][nf], al[mf], bh, acc[mf][nf]);
                    wmma::mma_sync(acc[mf][nf], ah[mf], bl, acc[mf][nf]);
                }
            }
        }
        __syncthreads();   // all reads of buf done before next iteration's load overwrites it
    }

    // ---- epilogue via per-warp smem staging ----
    float* wstage = stage_epi + wid * (16 * 20);
#pragma unroll
    for (int mf = 0; mf < MFRAG; mf++) {
#pragma unroll
        for (int nf = 0; nf < NFRAG; nf++) {
            wmma::store_matrix_sync(wstage, acc[mf][nf], 20, wmma::mem_row_major);
            __syncwarp();
            int r = lid >> 1, c0 = (lid & 1) << 3;
            long grow = rowBase + wm * WM + mf * 16 + r;
            int gcol = n0 + wn * WN + nf * 16 + c0;
            const float4* bp = (const float4*)&bias[gcol];
            float4 b0 = bp[0], b1 = bp[1];
            float v[8];
            v[0] = wstage[r * 20 + c0 + 0] + b0.x;
            v[1] = wstage[r * 20 + c0 + 1] + b0.y;
            v[2] = wstage[r * 20 + c0 + 2] + b0.z;
            v[3] = wstage[r * 20 + c0 + 3] + b0.w;
            v[4] = wstage[r * 20 + c0 + 4] + b1.x;
            v[5] = wstage[r * 20 + c0 + 5] + b1.y;
            v[6] = wstage[r * 20 + c0 + 6] + b1.z;
            v[7] = wstage[r * 20 + c0 + 7] + b1.w;
            if (DOTANH) {
#pragma unroll
                for (int j = 0; j < 8; j++) v[j] = tanhf(v[j]);
            }
            if (OUTMODE != 1) {
                float4* cp = (float4*)&C[grow * N + gcol];
                cp[0] = make_float4(v[0], v[1], v[2], v[3]);
                cp[1] = make_float4(v[4], v[5], v[6], v[7]);
            }
            if (OUTMODE >= 1) {
                __nv_bfloat16 h[8];
                uint4 uh, ul;
#pragma unroll
                for (int j = 0; j < 8; j++) h[j] = __float2bfloat16(v[j]);
                uh.x = pack_bf2(h[0], h[1]); uh.y = pack_bf2(h[2], h[3]);
                uh.z = pack_bf2(h[4], h[5]); uh.w = pack_bf2(h[6], h[7]);
                __nv_bfloat16 l[8];
#pragma unroll
                for (int j = 0; j < 8; j++)
                    l[j] = __float2bfloat16(v[j] - __bfloat162float(h[j]));
                ul.x = pack_bf2(l[0], l[1]); ul.y = pack_bf2(l[2], l[3]);
                ul.z = pack_bf2(l[4], l[5]); ul.w = pack_bf2(l[6], l[7]);
                *(uint4*)&Chi[grow * N + gcol] = uh;
                *(uint4*)&Clo[grow * N + gcol] = ul;
            }
            __syncwarp();
        }
    }
}

// ---------------- init: zero all per-launch accumulators ----------------
__global__ void init_kernel() {
    int t = threadIdx.x;
    for (int i = t; i < NCLS * NCONS; i += blockDim.x) g_msum[i] = 0.f;
    if (t < NCLS) { g_T[t] = 0.f; g_cnt[t] = 0; g_cur[t] = 0; }
    if (t == 0) g_cdiff = 0.f;
}

// ---------------- per-point / per-class statistics ----------------
__global__ void stats_kernel(const float* __restrict__ x) {
    __shared__ float sm[NCLS * NCONS];
    __shared__ float sT[NCLS];
    __shared__ int   sC[NCLS];
    int tid = threadIdx.x;
    for (int i = tid; i < NCLS * NCONS; i += blockDim.x) sm[i] = 0.f;
    if (tid < NCLS) { sT[tid] = 0.f; sC[tid] = 0; }
    __syncthreads();

    int i = blockIdx.x * blockDim.x + tid;       // exact coverage (32*256 = 8192)
    int l = (int)x[(long)i * (DIN + 1)];
    const float* e = g_emb + (long)i * EMBD + NEFF;
    float sq = 0.f;
#pragma unroll
    for (int d = 0; d < NCONS; d++) {
        float v = e[d];
        sq += v * v;
        atomicAdd(&sm[l * NCONS + d], v);
    }
    g_sq[i] = sq;
    g_lbl[i] = l;
    atomicAdd(&sT[l], sq);
    atomicAdd(&sC[l], 1);
    __syncthreads();

    for (int j = tid; j < NCLS * NCONS; j += blockDim.x) atomicAdd(&g_msum[j], sm[j]);
    if (tid < NCLS) {
        atomicAdd(&g_T[tid], sT[tid]);
        atomicAdd(&g_cnt[tid], sC[tid]);
    }
}

// ---------------- counting-sort offsets + tile offsets ----------------
__global__ void offsets_kernel() {
    if (threadIdx.x == 0 && blockIdx.x == 0) {
        int acc = 0, tacc = 0;
        for (int k = 0; k < NCLS; k++) {
            g_off[k] = acc; acc += g_cnt[k];
            g_cur[k] = 0;
            int t = (g_cnt[k] + 31) >> 5;
            g_tileoff[k] = tacc; tacc += t * t;
        }
        g_off[NCLS] = acc;
        g_tileoff[NCLS] = tacc;
    }
}

__global__ void scatter_kernel() {
    int i = blockIdx.x * blockDim.x + threadIdx.x;
    int l = g_lbl[i];
    int pos = g_off[l] + atomicAdd(&g_cur[l], 1);
    g_perm[pos] = i;
}

// ---------------- same-class pairwise C_diff (persistent tile loop) ----------------
__global__ __launch_bounds__(256)
void pairwise_kernel() {
    __shared__ float Ci[32][NCONS + 1];   // pad to 63: conflict-free
    __shared__ float Cj[32][NCONS + 1];
    __shared__ float sqi[32], sqj[32];
    __shared__ float red[256];

    int tid = threadIdx.x;
    int total = g_tileoff[NCLS];
    float accT = 0.f;

    for (int w = blockIdx.x; w < total; w += gridDim.x) {
        int k = 0;
        while (g_tileoff[k + 1] <= w) k++;
        int n = g_cnt[k];
        int tpd = (n + 31) >> 5;
        int local = w - g_tileoff[k];
        int ti = local / tpd, tj = local % tpd;
        int base = g_off[k];
        int ni = min(32, n - ti * 32);
        int nj = min(32, n - tj * 32);

        __syncthreads();   // protect shared reuse across tiles
        for (int idx = tid; idx < 32 * NCONS; idx += blockDim.x) {
            int r = idx / NCONS, d = idx % NCONS;
            int a = ti * 32 + r;
            if (a < n) {
                int gi = g_perm[base + a];
                Ci[r][d] = g_emb[(long)gi * EMBD + NEFF + d];
                if (d == 0) sqi[r] = g_sq[gi];
            }
            int b = tj * 32 + r;
            if (b < n) {
                int gj = g_perm[base + b];
                Cj[r][d] = g_emb[(long)gj * EMBD + NEFF + d];
                if (d == 0) sqj[r] = g_sq[gj];
            }
        }
        __syncthreads();

        int b = tid & 31;        // varies across warp -> conflict-free Cj reads
        int a0 = tid >> 5;       // uniform across warp -> broadcast Ci reads
        if (b < nj) {
            float dot0 = 0.f, dot1 = 0.f, dot2 = 0.f, dot3 = 0.f;
#pragma unroll
            for (int d = 0; d < NCONS; d++) {
                float cj = Cj[b][d];
                dot0 += Ci[a0][d] * cj;
                dot1 += Ci[a0 + 8][d] * cj;
                dot2 += Ci[a0 + 16][d] * cj;
                dot3 += Ci[a0 + 24][d] * cj;
            }
            float sj = sqj[b];
            float dots[4] = {dot0, dot1, dot2, dot3};
#pragma unroll
            for (int m = 0; m < 4; m++) {
                int a = a0 + m * 8;
                if (a < ni) {
                    float D = fmaxf(sqi[a] + sj - 2.f * dots[m], 0.f) * (1.f / NCONS);
                    float t = MARGIN - D;
                    if (t > 0.f) accT += t;
                }
            }
        }
    }

    red[tid] = accT;
    __syncthreads();
    for (int s = 128; s > 0; s >>= 1) {
        if (tid < s) red[tid] += red[tid + s];
        __syncthreads();
    }
    if (tid == 0 && red[0] != 0.f) atomicAdd(&g_cdiff, red[0]);
}

// ---------------- finalize: parallel closed-form C_sim, normalize C_diff ----------------
__global__ void finalize_kernel(float* __restrict__ out) {
    __shared__ float Msh[NCONS];
    __shared__ float s_summ2, s_sumTw, s_MM;
    __shared__ unsigned long long s_n2;
    int tid = threadIdx.x;
    if (tid < NCONS) Msh[tid] = 0.f;
    if (tid == 0) { s_summ2 = 0.f; s_sumTw = 0.f; s_MM = 0.f; s_n2 = 0ull; }
    __syncthreads();

    float p2 = 0.f;
    for (int i = tid; i < NCLS * NCONS; i += blockDim.x) {
        float v = g_msum[i];
        p2 += v * v;
        atomicAdd(&Msh[i % NCONS], v);
    }
    if (p2 != 0.f) atomicAdd(&s_summ2, p2);
    if (tid < NCLS) {
        int n = g_cnt[tid];
        atomicAdd(&s_n2, (unsigned long long)n * (unsigned long long)n);
        atomicAdd(&s_sumTw, g_T[tid] * (float)(NPTS - n));
    }
    __syncthreads();
    if (tid < NCONS) atomicAdd(&s_MM, Msh[tid] * Msh[tid]);
    __syncthreads();

    if (tid == 0) {
        double ndiff = (double)NPTS * (double)NPTS - (double)s_n2;
        float raw = 2.f * s_sumTw - 2.f * (s_MM - s_summ2);
        float csim = raw * (1.f / NCONS) / (float)(ndiff + 1.0);
        float cdiff = g_cdiff / (float)((double)NPTS * (double)NPTS - ndiff + 1.0);
        out[(long)NPTS * DIN]     = csim;
        out[(long)NPTS * DIN + 1] = cdiff;
    }
}

// ---------------- launch ----------------
extern "C" void kernel_launch(void* const* d_in, const int* in_sizes, int n_in,
                              void* d_out, int out_size) {
    const float* x  = (const float*)d_in[0];
    const float* W1 = (const float*)d_in[1];
    const float* b1 = (const float*)d_in[2];
    const float* W2 = (const float*)d_in[3];
    const float* b2 = (const float*)d_in[4];
    const float* W3 = (const float*)d_in[5];
    const float* b3 = (const float*)d_in[6];
    const float* W4 = (const float*)d_in[7];
    const float* b4 = (const float*)d_in[8];
    float* out = (float*)d_out;

    void *pxh, *pxl, *p1h, *p1l, *p2h, *p2l, *p3h, *p3l, *p4h, *p4l;
    void *ph1h, *ph1l, *ph2h, *ph2l, *peh, *pel, *pemb;
    cudaGetSymbolAddress(&pxh, g_xhi);   cudaGetSymbolAddress(&pxl, g_xlo);
    cudaGetSymbolAddress(&p1h, g_w1hi);  cudaGetSymbolAddress(&p1l, g_w1lo);
    cudaGetSymbolAddress(&p2h, g_w2hi);  cudaGetSymbolAddress(&p2l, g_w2lo);
    cudaGetSymbolAddress(&p3h, g_w3hi);  cudaGetSymbolAddress(&p3l, g_w3lo);
    cudaGetSymbolAddress(&p4h, g_w4hi);  cudaGetSymbolAddress(&p4l, g_w4lo);
    cudaGetSymbolAddress(&ph1h, g_h1hi); cudaGetSymbolAddress(&ph1l, g_h1lo);
    cudaGetSymbolAddress(&ph2h, g_h2hi); cudaGetSymbolAddress(&ph2l, g_h2lo);
    cudaGetSymbolAddress(&peh, g_ehi);   cudaGetSymbolAddress(&pel, g_elo);
    cudaGetSymbolAddress(&pemb, g_emb);
    typedef __nv_bfloat16 bf;

    // dynamic smem sizes: 2 stages x (2*BM*40 + 2*32*(BN+8)) bf16
    const int SM128 = 2 * (2 * 128 * 40 + 2 * 32 * 136) * 2;   // 75776
    const int SM64  = 2 * (2 * 64 * 40 + 2 * 32 * 72) * 2;     // 38912
    (void)cudaFuncSetAttribute((const void*)hgemm_cp<128, 128, 32, 64, 1, true>,
                               cudaFuncAttributeMaxDynamicSharedMemorySize, SM128);
    (void)cudaFuncSetAttribute((const void*)hgemm_cp<128, 128, 32, 64, 0, false>,
                               cudaFuncAttributeMaxDynamicSharedMemorySize, SM128);
    (void)cudaFuncSetAttribute((const void*)hgemm_cp<64, 64, 16, 32, 2, false>,
                               cudaFuncAttributeMaxDynamicSharedMemorySize, SM64);

    init_kernel<<<1, 256>>>();

    split_x_kernel<<<NPTS * DIN / 256, 256>>>(x);
    split_w_kernel<<<DIN * HID / 256, 256>>>(W1, (bf*)p1h, (bf*)p1l, DIN * HID);
    split_w_kernel<<<HID * EMBD / 256, 256>>>(W2, (bf*)p2h, (bf*)p2l, HID * EMBD);
    split_w_kernel<<<EMBD * HID / 256, 256>>>(W3, (bf*)p3h, (bf*)p3l, EMBD * HID);
    split_w_kernel<<<HID * DIN / 256, 256>>>(W4, (bf*)p4h, (bf*)p4l, HID * DIN);

    // h1 = tanh(data @ W1 + b1) -> split bf16 only
    {
        dim3 grid(HID / 128, NPTS / 128);
        hgemm_cp<128, 128, 32, 64, 1, true><<<grid, 256, SM128>>>(
            (bf*)pxh, (bf*)pxl, (bf*)p1h, (bf*)p1l, b1,
            nullptr, (bf*)ph1h, (bf*)ph1l, DIN, HID);
    }
    // emb = h1 @ W2 + b2 -> fp32 + split
    {
        dim3 grid(EMBD / 64, NPTS / 64);
        hgemm_cp<64, 64, 16, 32, 2, false><<<grid, 256, SM64>>>(
            (bf*)ph1h, (bf*)ph1l, (bf*)p2h, (bf*)p2l, b2,
            (float*)pemb, (bf*)peh, (bf*)pel, HID, EMBD);
    }
    // h2 = tanh(emb @ W3 + b3) -> split bf16 only
    {
        dim3 grid(HID / 128, NPTS / 128);
        hgemm_cp<128, 128, 32, 64, 1, true><<<grid, 256, SM128>>>(
            (bf*)peh, (bf*)pel, (bf*)p3h, (bf*)p3l, b3,
            nullptr, (bf*)ph2h, (bf*)ph2l, EMBD, HID);
    }
    // decoded = h2 @ W4 + b4 -> fp32 out
    {
        dim3 grid(DIN / 128, NPTS / 128);
        hgemm_cp<128, 128, 32, 64, 0, false><<<grid, 256, SM128>>>(
            (bf*)ph2h, (bf*)ph2l, (bf*)p4h, (bf*)p4l, b4,
            out, nullptr, nullptr, HID, DIN);
    }

    stats_kernel<<<NPTS / 256, 256>>>(x);
    offsets_kernel<<<1, 32>>>();
    scatter_kernel<<<NPTS / 256, 256>>>();
    pairwise_kernel<<<4096, 256>>>();
    finalize_kernel<<<1, 256>>>(out);
}